// round 3
// baseline (speedup 1.0000x reference)
#include <cuda_runtime.h>
#include <cuda_bf16.h>
#include <cstdint>

// Problem constants (Qwen3MoeSparseMoeBlock_2413771621126)
#define T_TOK   1024
#define HID     2048
#define NEXP    16
#define TOPK    4
#define INTER   768
#define INTER2  1536

// ---------------- device scratch ----------------
__device__ int   g_cnt[NEXP];
__device__ int   g_tok[NEXP * T_TOK];
__device__ float g_wt [NEXP * T_TOK];
__device__ float g_h  [(size_t)NEXP * T_TOK * INTER];   // ~50.3 MB

// ---------------- helpers ----------------
// bf16x2 split of float4 -> hi (uint2), lo (uint2)
__device__ __forceinline__ void split4(float4 f, uint2& hi, uint2& lo) {
    __nv_bfloat16 hx = __float2bfloat16(f.x);
    __nv_bfloat16 hy = __float2bfloat16(f.y);
    __nv_bfloat16 hz = __float2bfloat16(f.z);
    __nv_bfloat16 hw = __float2bfloat16(f.w);
    __nv_bfloat16 lx = __float2bfloat16(f.x - __bfloat162float(hx));
    __nv_bfloat16 ly = __float2bfloat16(f.y - __bfloat162float(hy));
    __nv_bfloat16 lz = __float2bfloat16(f.z - __bfloat162float(hz));
    __nv_bfloat16 lw = __float2bfloat16(f.w - __bfloat162float(hw));
    hi.x = ((uint32_t)__bfloat16_as_ushort(hy) << 16) | __bfloat16_as_ushort(hx);
    hi.y = ((uint32_t)__bfloat16_as_ushort(hw) << 16) | __bfloat16_as_ushort(hz);
    lo.x = ((uint32_t)__bfloat16_as_ushort(ly) << 16) | __bfloat16_as_ushort(lx);
    lo.y = ((uint32_t)__bfloat16_as_ushort(lw) << 16) | __bfloat16_as_ushort(lz);
}
__device__ __forceinline__ void split1(float f, uint16_t& hi, uint16_t& lo) {
    __nv_bfloat16 h = __float2bfloat16(f);
    __nv_bfloat16 l = __float2bfloat16(f - __bfloat162float(h));
    hi = __bfloat16_as_ushort(h);
    lo = __bfloat16_as_ushort(l);
}

#define MMA_BF16(d, a, b) \
    asm volatile("mma.sync.aligned.m16n8k16.row.col.f32.bf16.bf16.f32 " \
        "{%0,%1,%2,%3}, {%4,%5,%6,%7}, {%8,%9}, {%0,%1,%2,%3};" \
        : "+f"((d)[0]), "+f"((d)[1]), "+f"((d)[2]), "+f"((d)[3]) \
        : "r"((a)[0]), "r"((a)[1]), "r"((a)[2]), "r"((a)[3]), \
          "r"((b)[0]), "r"((b)[1]))

// A fragment (m16 x k16) from [m][k] bf16 smem with row pitch 40 elems
__device__ __forceinline__ void lda_frag(uint32_t a[4], const uint16_t* base, int row, int col) {
    a[0] = *reinterpret_cast<const uint32_t*>(base + (row    ) * 40 + col    );
    a[1] = *reinterpret_cast<const uint32_t*>(base + (row + 8) * 40 + col    );
    a[2] = *reinterpret_cast<const uint32_t*>(base + (row    ) * 40 + col + 8);
    a[3] = *reinterpret_cast<const uint32_t*>(base + (row + 8) * 40 + col + 8);
}
// B fragment (k16 x n8) from [n][k] bf16 smem with row pitch 40 elems
__device__ __forceinline__ void ldb_frag(uint32_t b[2], const uint16_t* base, int nrow, int col) {
    b[0] = *reinterpret_cast<const uint32_t*>(base + nrow * 40 + col    );
    b[1] = *reinterpret_cast<const uint32_t*>(base + nrow * 40 + col + 8);
}

// ---------------- phase 0 ----------------
__global__ void zero_kernel(float* __restrict__ out, int n) {
    int i = blockIdx.x * blockDim.x + threadIdx.x;
    if (i < n) out[i] = 0.0f;
    if (blockIdx.x == 0 && threadIdx.x < NEXP) g_cnt[threadIdx.x] = 0;
}

// ---------------- phase 1: router ----------------
__global__ void __launch_bounds__(128) router_kernel(
    const float* __restrict__ x, const float* __restrict__ rw)
{
    int t = blockIdx.x, tid = threadIdx.x;
    float acc[NEXP];
#pragma unroll
    for (int e = 0; e < NEXP; e++) acc[e] = 0.0f;
    const float* xr = x + (size_t)t * HID;
    for (int k = tid; k < HID; k += 128) {
        float xv = xr[k];
#pragma unroll
        for (int e = 0; e < NEXP; e++) acc[e] += xv * rw[e * HID + k];
    }
#pragma unroll
    for (int e = 0; e < NEXP; e++) {
#pragma unroll
        for (int off = 16; off > 0; off >>= 1)
            acc[e] += __shfl_down_sync(0xFFFFFFFFu, acc[e], off);
    }
    __shared__ float spart[4][NEXP];
    int warp = tid >> 5, lane = tid & 31;
    if (lane == 0) {
#pragma unroll
        for (int e = 0; e < NEXP; e++) spart[warp][e] = acc[e];
    }
    __syncthreads();
    if (tid == 0) {
        float logit[NEXP];
#pragma unroll
        for (int e = 0; e < NEXP; e++)
            logit[e] = spart[0][e] + spart[1][e] + spart[2][e] + spart[3][e];
        int idx[TOPK]; float val[TOPK]; bool used[NEXP];
#pragma unroll
        for (int e = 0; e < NEXP; e++) used[e] = false;
#pragma unroll
        for (int k = 0; k < TOPK; k++) {
            float best = -1e30f; int bi = 0;
            for (int e = 0; e < NEXP; e++)
                if (!used[e] && logit[e] > best) { best = logit[e]; bi = e; }
            used[bi] = true; idx[k] = bi; val[k] = best;
        }
        float mx = val[0], s = 0.0f, ev[TOPK];
#pragma unroll
        for (int k = 0; k < TOPK; k++) { ev[k] = expf(val[k] - mx); s += ev[k]; }
        float inv = 1.0f / s;
#pragma unroll
        for (int k = 0; k < TOPK; k++) {
            int e = idx[k];
            int pos = atomicAdd(&g_cnt[e], 1);
            g_tok[e * T_TOK + pos] = t;
            g_wt [e * T_TOK + pos] = ev[k] * inv;
        }
    }
}

// ============================================================
// smem layout per buffer (bytes), pitch 40 bf16 per row (80B):
//  gate_up: AH 0..10240, AL 10240..20480, BH 20480..30720, BL 30720..40960
//           (B rows: 0-63 gate n, 64-127 up n)
//  down:    AH 0, AL 10240, BH 20480 (5120), BL 25600; stage 30720
// ============================================================
#define GU_STAGE 40960
#define GU_SMEM  (2 * GU_STAGE)
#define DN_STAGE 30720
#define DN_SMEM  (2 * DN_STAGE)

// ---------------- phase 2: gate_up HMMA ----------------
__global__ void __launch_bounds__(256) gateup_mma(
    const float* __restrict__ x, const float* __restrict__ gup)
{
    extern __shared__ char smem[];
    int e = blockIdx.z;
    int cnt = g_cnt[e];
    int mbase = blockIdx.y * 128;
    if (mbase >= cnt) return;
    int nbase = blockIdx.x * 64;

    int tid = threadIdx.x;
    int lane = tid & 31, wid = tid >> 5;
    int wm = (wid & 3) * 32;          // warp M offset
    int wn = (wid >> 2) * 32;         // warp N offset (inter)

    // token indices for the 4 A-load rows handled by this thread
    int am = tid >> 3;                // 0..31
    int akq = (tid & 7) * 4;          // 0..28
    int tokv[4];
#pragma unroll
    for (int it = 0; it < 4; it++) {
        int m = am + it * 32;
        int gm = mbase + m;
        tokv[it] = (gm < cnt) ? g_tok[e * T_TOK + gm] : 0;
    }
    // B-load coords per iteration
    // idx = tid + it*256; mat = idx>>9; rem = idx&511; k = rem>>4; nq = (rem&15)*4

    float accG[2][4][4], accU[2][4][4];
#pragma unroll
    for (int i = 0; i < 2; i++)
#pragma unroll
        for (int j = 0; j < 4; j++)
#pragma unroll
            for (int c = 0; c < 4; c++) { accG[i][j][c] = 0.0f; accU[i][j][c] = 0.0f; }

    const int S = HID / 32;   // 64
    float4 ra[4], rb[4];

    // prologue: stage 0 direct
    {
#pragma unroll
        for (int it = 0; it < 4; it++)
            ra[it] = *reinterpret_cast<const float4*>(&x[(size_t)tokv[it] * HID + 0 + akq]);
#pragma unroll
        for (int it = 0; it < 4; it++) {
            int idx = tid + it * 256;
            int mat = idx >> 9, rem = idx & 511;
            int k = rem >> 4, nq = (rem & 15) * 4;
            rb[it] = *reinterpret_cast<const float4*>(
                &gup[((size_t)e * HID + k) * INTER2 + nbase + nq + mat * INTER]);
        }
        uint16_t* AH = (uint16_t*)(smem);
        uint16_t* AL = (uint16_t*)(smem + 10240);
        uint16_t* BH = (uint16_t*)(smem + 20480);
        uint16_t* BL = (uint16_t*)(smem + 30720);
#pragma unroll
        for (int it = 0; it < 4; it++) {
            int m = am + it * 32;
            uint2 hi, lo; split4(ra[it], hi, lo);
            *reinterpret_cast<uint2*>(AH + m * 40 + akq) = hi;
            *reinterpret_cast<uint2*>(AL + m * 40 + akq) = lo;
        }
#pragma unroll
        for (int it = 0; it < 4; it++) {
            int idx = tid + it * 256;
            int mat = idx >> 9, rem = idx & 511;
            int k = rem >> 4, nq = (rem & 15) * 4;
            float fv[4] = {rb[it].x, rb[it].y, rb[it].z, rb[it].w};
#pragma unroll
            for (int j = 0; j < 4; j++) {
                uint16_t h, l; split1(fv[j], h, l);
                int row = mat * 64 + nq + j;
                BH[row * 40 + k] = h;
                BL[row * 40 + k] = l;
            }
        }
    }
    __syncthreads();

#pragma unroll 1
    for (int s = 0; s < S; s++) {
        int b = s & 1;
        bool more = (s + 1 < S);
        int k0n = (s + 1) * 32;
        // issue next-stage LDGs (fly during mma)
        if (more) {
#pragma unroll
            for (int it = 0; it < 4; it++)
                ra[it] = *reinterpret_cast<const float4*>(&x[(size_t)tokv[it] * HID + k0n + akq]);
#pragma unroll
            for (int it = 0; it < 4; it++) {
                int idx = tid + it * 256;
                int mat = idx >> 9, rem = idx & 511;
                int k = rem >> 4, nq = (rem & 15) * 4;
                rb[it] = *reinterpret_cast<const float4*>(
                    &gup[((size_t)e * HID + k0n + k) * INTER2 + nbase + nq + mat * INTER]);
            }
        }
        // MMA on buffer b
        {
            const uint16_t* AH = (const uint16_t*)(smem + b * GU_STAGE);
            const uint16_t* AL = (const uint16_t*)(smem + b * GU_STAGE + 10240);
            const uint16_t* BH = (const uint16_t*)(smem + b * GU_STAGE + 20480);
            const uint16_t* BL = (const uint16_t*)(smem + b * GU_STAGE + 30720);
#pragma unroll
            for (int ks = 0; ks < 2; ks++) {
                int col = ks * 16 + (lane & 3) * 2;
                uint32_t ah[2][4], al[2][4];
#pragma unroll
                for (int mt = 0; mt < 2; mt++) {
                    int row = wm + mt * 16 + (lane >> 2);
                    lda_frag(ah[mt], AH, row, col);
                    lda_frag(al[mt], AL, row, col);
                }
#pragma unroll
                for (int nt = 0; nt < 4; nt++) {
                    int ng = wn + nt * 8 + (lane >> 2);      // gate row
                    uint32_t bgh[2], bgl[2], buh[2], bul[2];
                    ldb_frag(bgh, BH, ng, col);
                    ldb_frag(bgl, BL, ng, col);
                    ldb_frag(buh, BH, ng + 64, col);
                    ldb_frag(bul, BL, ng + 64, col);
#pragma unroll
                    for (int mt = 0; mt < 2; mt++) {
                        MMA_BF16(accG[mt][nt], ah[mt], bgh);
                        MMA_BF16(accG[mt][nt], ah[mt], bgl);
                        MMA_BF16(accG[mt][nt], al[mt], bgh);
                        MMA_BF16(accU[mt][nt], ah[mt], buh);
                        MMA_BF16(accU[mt][nt], ah[mt], bul);
                        MMA_BF16(accU[mt][nt], al[mt], buh);
                    }
                }
            }
        }
        // split + STS next stage
        if (more) {
            int nb = (s + 1) & 1;
            uint16_t* AH = (uint16_t*)(smem + nb * GU_STAGE);
            uint16_t* AL = (uint16_t*)(smem + nb * GU_STAGE + 10240);
            uint16_t* BH = (uint16_t*)(smem + nb * GU_STAGE + 20480);
            uint16_t* BL = (uint16_t*)(smem + nb * GU_STAGE + 30720);
#pragma unroll
            for (int it = 0; it < 4; it++) {
                int m = am + it * 32;
                uint2 hi, lo; split4(ra[it], hi, lo);
                *reinterpret_cast<uint2*>(AH + m * 40 + akq) = hi;
                *reinterpret_cast<uint2*>(AL + m * 40 + akq) = lo;
            }
#pragma unroll
            for (int it = 0; it < 4; it++) {
                int idx = tid + it * 256;
                int mat = idx >> 9, rem = idx & 511;
                int k = rem >> 4, nq = (rem & 15) * 4;
                float fv[4] = {rb[it].x, rb[it].y, rb[it].z, rb[it].w};
#pragma unroll
                for (int j = 0; j < 4; j++) {
                    uint16_t h, l; split1(fv[j], h, l);
                    int row = mat * 64 + nq + j;
                    BH[row * 40 + k] = h;
                    BL[row * 40 + k] = l;
                }
            }
        }
        __syncthreads();
    }

    // epilogue: h = silu(gate) * up * wt -> g_h
#pragma unroll
    for (int mt = 0; mt < 2; mt++) {
#pragma unroll
        for (int half = 0; half < 2; half++) {
            int m = wm + mt * 16 + (lane >> 2) + half * 8;
            int gm = mbase + m;
            if (gm >= cnt) continue;
            float w = g_wt[e * T_TOK + gm];
            float* hp = &g_h[((size_t)e * T_TOK + gm) * INTER + nbase];
#pragma unroll
            for (int nt = 0; nt < 4; nt++) {
                int col = wn + nt * 8 + (lane & 3) * 2;
                float g0 = accG[mt][nt][half * 2 + 0], u0 = accU[mt][nt][half * 2 + 0];
                float g1 = accG[mt][nt][half * 2 + 1], u1 = accU[mt][nt][half * 2 + 1];
                float2 hv;
                hv.x = (g0 / (1.0f + expf(-g0))) * u0 * w;
                hv.y = (g1 / (1.0f + expf(-g1))) * u1 * w;
                *reinterpret_cast<float2*>(hp + col) = hv;
            }
        }
    }
}

// ---------------- phase 3: down HMMA + atomic scatter ----------------
__global__ void __launch_bounds__(256) down_mma(
    const float* __restrict__ dw, float* __restrict__ out)
{
    extern __shared__ char smem[];
    int e = blockIdx.z;
    int cnt = g_cnt[e];
    int mbase = blockIdx.y * 128;
    if (mbase >= cnt) return;
    int nbase = blockIdx.x * 64;

    int tid = threadIdx.x;
    int lane = tid & 31, wid = tid >> 5;
    int wm = (wid & 3) * 32;
    int wn = (wid >> 2) * 32;

    int am = tid >> 3;
    int akq = (tid & 7) * 4;

    float acc[2][4][4];
#pragma unroll
    for (int i = 0; i < 2; i++)
#pragma unroll
        for (int j = 0; j < 4; j++)
#pragma unroll
            for (int c = 0; c < 4; c++) acc[i][j][c] = 0.0f;

    const int S = INTER / 32;  // 24
    float4 ra[4], rb[2];

    {
#pragma unroll
        for (int it = 0; it < 4; it++) {
            int m = am + it * 32;
            ra[it] = *reinterpret_cast<const float4*>(
                &g_h[((size_t)e * T_TOK + mbase + m) * INTER + 0 + akq]);
        }
#pragma unroll
        for (int it = 0; it < 2; it++) {
            int idx = tid + it * 256;
            int k = idx >> 4, nq = (idx & 15) * 4;
            rb[it] = *reinterpret_cast<const float4*>(
                &dw[((size_t)e * INTER + k) * HID + nbase + nq]);
        }
        uint16_t* AH = (uint16_t*)(smem);
        uint16_t* AL = (uint16_t*)(smem + 10240);
        uint16_t* BH = (uint16_t*)(smem + 20480);
        uint16_t* BL = (uint16_t*)(smem + 25600);
#pragma unroll
        for (int it = 0; it < 4; it++) {
            int m = am + it * 32;
            uint2 hi, lo; split4(ra[it], hi, lo);
            *reinterpret_cast<uint2*>(AH + m * 40 + akq) = hi;
            *reinterpret_cast<uint2*>(AL + m * 40 + akq) = lo;
        }
#pragma unroll
        for (int it = 0; it < 2; it++) {
            int idx = tid + it * 256;
            int k = idx >> 4, nq = (idx & 15) * 4;
            float fv[4] = {rb[it].x, rb[it].y, rb[it].z, rb[it].w};
#pragma unroll
            for (int j = 0; j < 4; j++) {
                uint16_t h, l; split1(fv[j], h, l);
                BH[(nq + j) * 40 + k] = h;
                BL[(nq + j) * 40 + k] = l;
            }
        }
    }
    __syncthreads();

#pragma unroll 1
    for (int s = 0; s < S; s++) {
        int b = s & 1;
        bool more = (s + 1 < S);
        int k0n = (s + 1) * 32;
        if (more) {
#pragma unroll
            for (int it = 0; it < 4; it++) {
                int m = am + it * 32;
                ra[it] = *reinterpret_cast<const float4*>(
                    &g_h[((size_t)e * T_TOK + mbase + m) * INTER + k0n + akq]);
            }
#pragma unroll
            for (int it = 0; it < 2; it++) {
                int idx = tid + it * 256;
                int k = idx >> 4, nq = (idx & 15) * 4;
                rb[it] = *reinterpret_cast<const float4*>(
                    &dw[((size_t)e * INTER + k0n + k) * HID + nbase + nq]);
            }
        }
        {
            const uint16_t* AH = (const uint16_t*)(smem + b * DN_STAGE);
            const uint16_t* AL = (const uint16_t*)(smem + b * DN_STAGE + 10240);
            const uint16_t* BH = (const uint16_t*)(smem + b * DN_STAGE + 20480);
            const uint16_t* BL = (const uint16_t*)(smem + b * DN_STAGE + 25600);
#pragma unroll
            for (int ks = 0; ks < 2; ks++) {
                int col = ks * 16 + (lane & 3) * 2;
                uint32_t ah[2][4], al[2][4];
#pragma unroll
                for (int mt = 0; mt < 2; mt++) {
                    int row = wm + mt * 16 + (lane >> 2);
                    lda_frag(ah[mt], AH, row, col);
                    lda_frag(al[mt], AL, row, col);
                }
#pragma unroll
                for (int nt = 0; nt < 4; nt++) {
                    int nr = wn + nt * 8 + (lane >> 2);
                    uint32_t bh[2], bl[2];
                    ldb_frag(bh, BH, nr, col);
                    ldb_frag(bl, BL, nr, col);
#pragma unroll
                    for (int mt = 0; mt < 2; mt++) {
                        MMA_BF16(acc[mt][nt], ah[mt], bh);
                        MMA_BF16(acc[mt][nt], ah[mt], bl);
                        MMA_BF16(acc[mt][nt], al[mt], bh);
                    }
                }
            }
        }
        if (more) {
            int nb = (s + 1) & 1;
            uint16_t* AH = (uint16_t*)(smem + nb * DN_STAGE);
            uint16_t* AL = (uint16_t*)(smem + nb * DN_STAGE + 10240);
            uint16_t* BH = (uint16_t*)(smem + nb * DN_STAGE + 20480);
            uint16_t* BL = (uint16_t*)(smem + nb * DN_STAGE + 25600);
#pragma unroll
            for (int it = 0; it < 4; it++) {
                int m = am + it * 32;
                uint2 hi, lo; split4(ra[it], hi, lo);
                *reinterpret_cast<uint2*>(AH + m * 40 + akq) = hi;
                *reinterpret_cast<uint2*>(AL + m * 40 + akq) = lo;
            }
#pragma unroll
            for (int it = 0; it < 2; it++) {
                int idx = tid + it * 256;
                int k = idx >> 4, nq = (idx & 15) * 4;
                float fv[4] = {rb[it].x, rb[it].y, rb[it].z, rb[it].w};
#pragma unroll
                for (int j = 0; j < 4; j++) {
                    uint16_t h, l; split1(fv[j], h, l);
                    BH[(nq + j) * 40 + k] = h;
                    BL[(nq + j) * 40 + k] = l;
                }
            }
        }
        __syncthreads();
    }

    // epilogue: atomic scatter
#pragma unroll
    for (int mt = 0; mt < 2; mt++) {
#pragma unroll
        for (int half = 0; half < 2; half++) {
            int m = wm + mt * 16 + (lane >> 2) + half * 8;
            int gm = mbase + m;
            if (gm >= cnt) continue;
            int tok = g_tok[e * T_TOK + gm];
            float* op = &out[(size_t)tok * HID + nbase];
#pragma unroll
            for (int nt = 0; nt < 4; nt++) {
                int col = wn + nt * 8 + (lane & 3) * 2;
                atomicAdd(op + col,     acc[mt][nt][half * 2 + 0]);
                atomicAdd(op + col + 1, acc[mt][nt][half * 2 + 1]);
            }
        }
    }
}

// ---------------- launch ----------------
extern "C" void kernel_launch(void* const* d_in, const int* in_sizes, int n_in,
                              void* d_out, int out_size)
{
    const float* x    = (const float*)d_in[0];
    const float* rw   = (const float*)d_in[1];
    const float* gup  = (const float*)d_in[2];
    const float* dw   = (const float*)d_in[3];
    float* out = (float*)d_out;

    static bool attr_set = false;
    if (!attr_set) {
        cudaFuncSetAttribute(gateup_mma, cudaFuncAttributeMaxDynamicSharedMemorySize, GU_SMEM);
        cudaFuncSetAttribute(down_mma,   cudaFuncAttributeMaxDynamicSharedMemorySize, DN_SMEM);
        attr_set = true;
    }

    int n_out = T_TOK * HID;
    zero_kernel<<<(n_out + 511) / 512, 512>>>(out, n_out);
    router_kernel<<<T_TOK, 128>>>(x, rw);

    dim3 gridG(INTER / 64, T_TOK / 128, NEXP);   // (12, 8, 16)
    gateup_mma<<<gridG, 256, GU_SMEM>>>(x, gup);

    dim3 gridD(HID / 64, T_TOK / 128, NEXP);     // (32, 8, 16)
    down_mma<<<gridD, 256, DN_SMEM>>>(dw, out);
}

// round 4
// speedup vs baseline: 2.4443x; 2.4443x over previous
#include <cuda_runtime.h>
#include <cuda_bf16.h>
#include <cstdint>

// Problem constants (Qwen3MoeSparseMoeBlock_2413771621126)
#define T_TOK   1024
#define HID     2048
#define NEXP    16
#define TOPK    4
#define INTER   768
#define INTER2  1536

// ---------------- device scratch (static; allocation-free) ----------------
__device__ int   g_cnt[NEXP];
__device__ int   g_tok[NEXP * T_TOK];
__device__ float g_wt [NEXP * T_TOK];

__device__ __align__(128) __nv_bfloat16 g_xhi[(size_t)T_TOK * HID];
__device__ __align__(128) __nv_bfloat16 g_xlo[(size_t)T_TOK * HID];
__device__ __align__(128) __nv_bfloat16 g_ghi[(size_t)NEXP * HID * INTER2];
__device__ __align__(128) __nv_bfloat16 g_glo[(size_t)NEXP * HID * INTER2];
__device__ __align__(128) __nv_bfloat16 g_dhi[(size_t)NEXP * INTER * HID];
__device__ __align__(128) __nv_bfloat16 g_dlo[(size_t)NEXP * INTER * HID];
__device__ __align__(128) __nv_bfloat16 g_hhi[(size_t)NEXP * T_TOK * INTER];
__device__ __align__(128) __nv_bfloat16 g_hlo[(size_t)NEXP * T_TOK * INTER];

// ---------------- helpers ----------------
__device__ __forceinline__ uint32_t smem_u32(const void* p) {
    uint32_t a;
    asm("{ .reg .u64 t; cvta.to.shared.u64 t, %1; cvt.u32.u64 %0, t; }" : "=r"(a) : "l"(p));
    return a;
}

__device__ __forceinline__ void split4(float4 f, uint2& hi, uint2& lo) {
    __nv_bfloat16 hx = __float2bfloat16(f.x);
    __nv_bfloat16 hy = __float2bfloat16(f.y);
    __nv_bfloat16 hz = __float2bfloat16(f.z);
    __nv_bfloat16 hw = __float2bfloat16(f.w);
    __nv_bfloat16 lx = __float2bfloat16(f.x - __bfloat162float(hx));
    __nv_bfloat16 ly = __float2bfloat16(f.y - __bfloat162float(hy));
    __nv_bfloat16 lz = __float2bfloat16(f.z - __bfloat162float(hz));
    __nv_bfloat16 lw = __float2bfloat16(f.w - __bfloat162float(hw));
    hi.x = ((uint32_t)__bfloat16_as_ushort(hy) << 16) | __bfloat16_as_ushort(hx);
    hi.y = ((uint32_t)__bfloat16_as_ushort(hw) << 16) | __bfloat16_as_ushort(hz);
    lo.x = ((uint32_t)__bfloat16_as_ushort(ly) << 16) | __bfloat16_as_ushort(lx);
    lo.y = ((uint32_t)__bfloat16_as_ushort(lw) << 16) | __bfloat16_as_ushort(lz);
}
__device__ __forceinline__ void split1(float f, uint16_t& hi, uint16_t& lo) {
    __nv_bfloat16 h = __float2bfloat16(f);
    __nv_bfloat16 l = __float2bfloat16(f - __bfloat162float(h));
    hi = __bfloat16_as_ushort(h);
    lo = __bfloat16_as_ushort(l);
}

#define MMA_BF16(d, a, b) \
    asm volatile("mma.sync.aligned.m16n8k16.row.col.f32.bf16.bf16.f32 " \
        "{%0,%1,%2,%3}, {%4,%5,%6,%7}, {%8,%9}, {%0,%1,%2,%3};" \
        : "+f"((d)[0]), "+f"((d)[1]), "+f"((d)[2]), "+f"((d)[3]) \
        : "r"((a)[0]), "r"((a)[1]), "r"((a)[2]), "r"((a)[3]), \
          "r"((b)[0]), "r"((b)[1]))

#define LDSM4(r, a) \
    asm volatile("ldmatrix.sync.aligned.m8n8.x4.shared.b16 {%0,%1,%2,%3}, [%4];" \
        : "=r"((r)[0]), "=r"((r)[1]), "=r"((r)[2]), "=r"((r)[3]) : "r"(a))
#define LDSM4T(r, a) \
    asm volatile("ldmatrix.sync.aligned.m8n8.x4.trans.shared.b16 {%0,%1,%2,%3}, [%4];" \
        : "=r"((r)[0]), "=r"((r)[1]), "=r"((r)[2]), "=r"((r)[3]) : "r"(a))

#define CP16(dst, src) \
    asm volatile("cp.async.cg.shared.global [%0], [%1], 16;" \
        :: "r"(dst), "l"(__cvta_generic_to_global(src)))
#define CP_COMMIT() asm volatile("cp.async.commit_group;" ::: "memory")
#define CP_WAIT0()  asm volatile("cp.async.wait_group 0;" ::: "memory")

// ---------------- phase 0 ----------------
__global__ void zero_kernel(float* __restrict__ out, int n) {
    int i = blockIdx.x * blockDim.x + threadIdx.x;
    if (i < n) out[i] = 0.0f;
    if (blockIdx.x == 0 && threadIdx.x < NEXP) g_cnt[threadIdx.x] = 0;
}

// ---------------- split conversion (fp32 -> hi/lo bf16) ----------------
__global__ void __launch_bounds__(256) split_kernel(
    const float4* __restrict__ src, uint2* __restrict__ hi, uint2* __restrict__ lo, int n4)
{
    int i = blockIdx.x * blockDim.x + threadIdx.x;
    if (i < n4) {
        uint2 h, l;
        split4(src[i], h, l);
        hi[i] = h;
        lo[i] = l;
    }
}

// ---------------- phase 1: router ----------------
__global__ void __launch_bounds__(128) router_kernel(
    const float* __restrict__ x, const float* __restrict__ rw)
{
    int t = blockIdx.x, tid = threadIdx.x;
    float acc[NEXP];
#pragma unroll
    for (int e = 0; e < NEXP; e++) acc[e] = 0.0f;
    const float* xr = x + (size_t)t * HID;
    for (int k = tid; k < HID; k += 128) {
        float xv = xr[k];
#pragma unroll
        for (int e = 0; e < NEXP; e++) acc[e] += xv * rw[e * HID + k];
    }
#pragma unroll
    for (int e = 0; e < NEXP; e++) {
#pragma unroll
        for (int off = 16; off > 0; off >>= 1)
            acc[e] += __shfl_down_sync(0xFFFFFFFFu, acc[e], off);
    }
    __shared__ float spart[4][NEXP];
    int warp = tid >> 5, lane = tid & 31;
    if (lane == 0) {
#pragma unroll
        for (int e = 0; e < NEXP; e++) spart[warp][e] = acc[e];
    }
    __syncthreads();
    if (tid == 0) {
        float logit[NEXP];
#pragma unroll
        for (int e = 0; e < NEXP; e++)
            logit[e] = spart[0][e] + spart[1][e] + spart[2][e] + spart[3][e];
        int idx[TOPK]; float val[TOPK]; bool used[NEXP];
#pragma unroll
        for (int e = 0; e < NEXP; e++) used[e] = false;
#pragma unroll
        for (int k = 0; k < TOPK; k++) {
            float best = -1e30f; int bi = 0;
            for (int e = 0; e < NEXP; e++)
                if (!used[e] && logit[e] > best) { best = logit[e]; bi = e; }
            used[bi] = true; idx[k] = bi; val[k] = best;
        }
        float mx = val[0], s = 0.0f, ev[TOPK];
#pragma unroll
        for (int k = 0; k < TOPK; k++) { ev[k] = expf(val[k] - mx); s += ev[k]; }
        float inv = 1.0f / s;
#pragma unroll
        for (int k = 0; k < TOPK; k++) {
            int e = idx[k];
            int pos = atomicAdd(&g_cnt[e], 1);
            g_tok[e * T_TOK + pos] = t;
            g_wt [e * T_TOK + pos] = ev[k] * inv;
        }
    }
}

// ============================================================
// GEMM smem layouts (per stage, bytes):
//  A (128 x 32 bf16, pitch 80):  AH @ 0 (10240), AL @ 10240
//  gate_up B (32 x 128, pitch 272): BH @ 20480 (8704), BL @ 29184 ; stage 37888
//  down    B (32 x 64,  pitch 144): BH @ 20480 (4608), BL @ 25088 ; stage 29696
// ============================================================
#define GU_STAGE 37888
#define GU_SMEM  (2 * GU_STAGE + 1024)
#define DN_STAGE 29696
#define DN_SMEM  (2 * DN_STAGE + 1024)

// ---------------- phase 2: gate_up GEMM ----------------
__device__ __forceinline__ void gu_load(
    int e, int nbase, int k0, uint32_t sb, const int* stok, int tid)
{
#pragma unroll
    for (int i = 0; i < 2; i++) {
        int c = tid + i * 256;
        int row = c >> 2, seg = c & 3;
        int tok = stok[row];
        size_t off = (size_t)tok * HID + k0 + seg * 8;
        CP16(sb + row * 80 + seg * 16,          g_xhi + off);
        CP16(sb + 10240 + row * 80 + seg * 16,  g_xlo + off);
    }
#pragma unroll
    for (int i = 0; i < 2; i++) {
        int c = tid + i * 256;
        int k = c >> 4, seg = c & 15;
        size_t roff = ((size_t)e * HID + k0 + k) * INTER2;
        int col = (seg < 8) ? (nbase + seg * 8) : (INTER + nbase + (seg - 8) * 8);
        CP16(sb + 20480 + k * 272 + seg * 16, g_ghi + roff + col);
        CP16(sb + 29184 + k * 272 + seg * 16, g_glo + roff + col);
    }
}

__global__ void __launch_bounds__(256, 2) gateup_mma(int dummy)
{
    extern __shared__ char smem[];
    int e = blockIdx.z;
    int cnt = g_cnt[e];
    int mbase = blockIdx.y * 128;
    if (mbase >= cnt) return;
    int nbase = blockIdx.x * 64;

    int tid = threadIdx.x;
    int lane = tid & 31, wid = tid >> 5;
    int wm = (wid & 3) * 32;
    int wn = (wid >> 2) * 32;

    uint32_t sbase = smem_u32(smem);
    int*   stok = (int*)  (smem + 2 * GU_STAGE);
    float* swt  = (float*)(smem + 2 * GU_STAGE + 512);
    if (tid < 128) {
        int gm = mbase + tid;
        stok[tid] = (gm < cnt) ? g_tok[e * T_TOK + gm] : 0;
        swt[tid]  = (gm < cnt) ? g_wt [e * T_TOK + gm] : 0.0f;
    }
    __syncthreads();

    float accG[2][4][4], accU[2][4][4];
#pragma unroll
    for (int i = 0; i < 2; i++)
#pragma unroll
        for (int j = 0; j < 4; j++)
#pragma unroll
            for (int c = 0; c < 4; c++) { accG[i][j][c] = 0.0f; accU[i][j][c] = 0.0f; }

    const int S = HID / 32;   // 64
    gu_load(e, nbase, 0, sbase, stok, tid);
    CP_COMMIT();

#pragma unroll 1
    for (int s = 0; s < S; s++) {
        int b = s & 1;
        CP_WAIT0();
        __syncthreads();
        if (s + 1 < S) {
            gu_load(e, nbase, (s + 1) * 32, sbase + (b ^ 1) * GU_STAGE, stok, tid);
            CP_COMMIT();
        }
        uint32_t st = sbase + b * GU_STAGE;
#pragma unroll
        for (int ks = 0; ks < 2; ks++) {
            uint32_t ah[2][4], al[2][4];
#pragma unroll
            for (int mt = 0; mt < 2; mt++) {
                uint32_t aa = st + (wm + mt * 16 + (lane & 15)) * 80
                            + (ks * 16 + (lane >> 4) * 8) * 2;
                LDSM4(ah[mt], aa);
                LDSM4(al[mt], aa + 10240);
            }
#pragma unroll
            for (int ng = 0; ng < 2; ng++) {
                uint32_t ba = st + 20480 + (ks * 16 + (lane & 15)) * 272
                            + (wn + ng * 16 + (lane >> 4) * 8) * 2;
                uint32_t bgh[4], bgl[4], buh[4], bul[4];
                LDSM4T(bgh, ba);
                LDSM4T(bgl, ba + 8704);
                LDSM4T(buh, ba + 128);          // up cols at +64 elems
                LDSM4T(bul, ba + 128 + 8704);
#pragma unroll
                for (int half = 0; half < 2; half++) {
                    int j = ng * 2 + half;
#pragma unroll
                    for (int mt = 0; mt < 2; mt++) {
                        MMA_BF16(accG[mt][j], ah[mt], &bgh[half * 2]);
                        MMA_BF16(accG[mt][j], ah[mt], &bgl[half * 2]);
                        MMA_BF16(accG[mt][j], al[mt], &bgh[half * 2]);
                        MMA_BF16(accU[mt][j], ah[mt], &buh[half * 2]);
                        MMA_BF16(accU[mt][j], ah[mt], &bul[half * 2]);
                        MMA_BF16(accU[mt][j], al[mt], &buh[half * 2]);
                    }
                }
            }
        }
        __syncthreads();
    }

    // epilogue: h = silu(gate) * up * wt -> hi/lo bf16 global
#pragma unroll
    for (int mt = 0; mt < 2; mt++) {
#pragma unroll
        for (int j = 0; j < 4; j++) {
            int col = wn + (j >> 1) * 16 + (j & 1) * 8 + (lane & 3) * 2;
#pragma unroll
            for (int rh = 0; rh < 2; rh++) {
                int m = wm + mt * 16 + (lane >> 2) + rh * 8;
                int gm = mbase + m;
                if (gm >= cnt) continue;
                float w = swt[m];
                float g0 = accG[mt][j][rh * 2 + 0], u0 = accU[mt][j][rh * 2 + 0];
                float g1 = accG[mt][j][rh * 2 + 1], u1 = accU[mt][j][rh * 2 + 1];
                float h0 = (g0 / (1.0f + expf(-g0))) * u0 * w;
                float h1 = (g1 / (1.0f + expf(-g1))) * u1 * w;
                uint16_t h0h, h0l, h1h, h1l;
                split1(h0, h0h, h0l);
                split1(h1, h1h, h1l);
                size_t off = ((size_t)e * T_TOK + gm) * INTER + nbase + col;
                *reinterpret_cast<uint32_t*>(g_hhi + off) = (uint32_t)h0h | ((uint32_t)h1h << 16);
                *reinterpret_cast<uint32_t*>(g_hlo + off) = (uint32_t)h0l | ((uint32_t)h1l << 16);
            }
        }
    }
}

// ---------------- phase 3: down GEMM + atomic scatter ----------------
__device__ __forceinline__ void dn_load(
    int e, int mbase, int nbase, int k0, uint32_t sb, int tid)
{
#pragma unroll
    for (int i = 0; i < 2; i++) {
        int c = tid + i * 256;
        int row = c >> 2, seg = c & 3;
        size_t off = ((size_t)e * T_TOK + mbase + row) * INTER + k0 + seg * 8;
        CP16(sb + row * 80 + seg * 16,         g_hhi + off);
        CP16(sb + 10240 + row * 80 + seg * 16, g_hlo + off);
    }
    {
        int c = tid;
        int k = c >> 3, seg = c & 7;
        size_t off = ((size_t)e * INTER + k0 + k) * HID + nbase + seg * 8;
        CP16(sb + 20480 + k * 144 + seg * 16, g_dhi + off);
        CP16(sb + 25088 + k * 144 + seg * 16, g_dlo + off);
    }
}

__global__ void __launch_bounds__(256, 2) down_mma(float* __restrict__ out)
{
    extern __shared__ char smem[];
    int e = blockIdx.z;
    int cnt = g_cnt[e];
    int mbase = blockIdx.y * 128;
    if (mbase >= cnt) return;
    int nbase = blockIdx.x * 64;

    int tid = threadIdx.x;
    int lane = tid & 31, wid = tid >> 5;
    int wm = (wid & 3) * 32;
    int wn = (wid >> 2) * 32;

    uint32_t sbase = smem_u32(smem);
    int* stok = (int*)(smem + 2 * DN_STAGE);
    if (tid < 128) {
        int gm = mbase + tid;
        stok[tid] = (gm < cnt) ? g_tok[e * T_TOK + gm] : -1;
    }
    __syncthreads();

    float acc[2][4][4];
#pragma unroll
    for (int i = 0; i < 2; i++)
#pragma unroll
        for (int j = 0; j < 4; j++)
#pragma unroll
            for (int c = 0; c < 4; c++) acc[i][j][c] = 0.0f;

    const int S = INTER / 32;  // 24
    dn_load(e, mbase, nbase, 0, sbase, tid);
    CP_COMMIT();

#pragma unroll 1
    for (int s = 0; s < S; s++) {
        int b = s & 1;
        CP_WAIT0();
        __syncthreads();
        if (s + 1 < S) {
            dn_load(e, mbase, nbase, (s + 1) * 32, sbase + (b ^ 1) * DN_STAGE, tid);
            CP_COMMIT();
        }
        uint32_t st = sbase + b * DN_STAGE;
#pragma unroll
        for (int ks = 0; ks < 2; ks++) {
            uint32_t ah[2][4], al[2][4];
#pragma unroll
            for (int mt = 0; mt < 2; mt++) {
                uint32_t aa = st + (wm + mt * 16 + (lane & 15)) * 80
                            + (ks * 16 + (lane >> 4) * 8) * 2;
                LDSM4(ah[mt], aa);
                LDSM4(al[mt], aa + 10240);
            }
#pragma unroll
            for (int ng = 0; ng < 2; ng++) {
                uint32_t ba = st + 20480 + (ks * 16 + (lane & 15)) * 144
                            + (wn + ng * 16 + (lane >> 4) * 8) * 2;
                uint32_t bh[4], bl[4];
                LDSM4T(bh, ba);
                LDSM4T(bl, ba + 4608);
#pragma unroll
                for (int half = 0; half < 2; half++) {
                    int j = ng * 2 + half;
#pragma unroll
                    for (int mt = 0; mt < 2; mt++) {
                        MMA_BF16(acc[mt][j], ah[mt], &bh[half * 2]);
                        MMA_BF16(acc[mt][j], ah[mt], &bl[half * 2]);
                        MMA_BF16(acc[mt][j], al[mt], &bh[half * 2]);
                    }
                }
            }
        }
        __syncthreads();
    }

    // epilogue: atomic scatter into out
#pragma unroll
    for (int mt = 0; mt < 2; mt++) {
#pragma unroll
        for (int rh = 0; rh < 2; rh++) {
            int m = wm + mt * 16 + (lane >> 2) + rh * 8;
            int tok = stok[m];
            if (tok < 0) continue;
            float* op = &out[(size_t)tok * HID + nbase];
#pragma unroll
            for (int j = 0; j < 4; j++) {
                int col = wn + (j >> 1) * 16 + (j & 1) * 8 + (lane & 3) * 2;
                atomicAdd(op + col,     acc[mt][j][rh * 2 + 0]);
                atomicAdd(op + col + 1, acc[mt][j][rh * 2 + 1]);
            }
        }
    }
}

// ---------------- launch ----------------
extern "C" void kernel_launch(void* const* d_in, const int* in_sizes, int n_in,
                              void* d_out, int out_size)
{
    const float* x    = (const float*)d_in[0];
    const float* rw   = (const float*)d_in[1];
    const float* gup  = (const float*)d_in[2];
    const float* dw   = (const float*)d_in[3];
    float* out = (float*)d_out;

    static bool attr_set = false;
    if (!attr_set) {
        cudaFuncSetAttribute(gateup_mma, cudaFuncAttributeMaxDynamicSharedMemorySize, GU_SMEM);
        cudaFuncSetAttribute(down_mma,   cudaFuncAttributeMaxDynamicSharedMemorySize, DN_SMEM);
        attr_set = true;
    }

    int n_out = T_TOK * HID;
    zero_kernel<<<(n_out + 511) / 512, 512>>>(out, n_out);

    // preconversion (hi/lo bf16 split)
    {
        __nv_bfloat16 *xhi, *xlo, *ghi, *glo, *dhi, *dlo;
        cudaGetSymbolAddress((void**)&xhi, g_xhi);
        cudaGetSymbolAddress((void**)&xlo, g_xlo);
        cudaGetSymbolAddress((void**)&ghi, g_ghi);
        cudaGetSymbolAddress((void**)&glo, g_glo);
        cudaGetSymbolAddress((void**)&dhi, g_dhi);
        cudaGetSymbolAddress((void**)&dlo, g_dlo);

        int n4x = T_TOK * HID / 4;
        split_kernel<<<(n4x + 255) / 256, 256>>>(
            (const float4*)x, (uint2*)xhi, (uint2*)xlo, n4x);
        int n4g = NEXP * HID * INTER2 / 4;
        split_kernel<<<(n4g + 255) / 256, 256>>>(
            (const float4*)gup, (uint2*)ghi, (uint2*)glo, n4g);
        int n4d = NEXP * INTER * HID / 4;
        split_kernel<<<(n4d + 255) / 256, 256>>>(
            (const float4*)dw, (uint2*)dhi, (uint2*)dlo, n4d);
    }

    router_kernel<<<T_TOK, 128>>>(x, rw);

    dim3 gridG(INTER / 64, T_TOK / 128, NEXP);   // (12, 8, 16)
    gateup_mma<<<gridG, 256, GU_SMEM>>>(0);

    dim3 gridD(HID / 64, T_TOK / 128, NEXP);     // (32, 8, 16)
    down_mma<<<gridD, 256, DN_SMEM>>>(out);
}

// round 5
// speedup vs baseline: 2.4493x; 1.0021x over previous
#include <cuda_runtime.h>
#include <cuda_bf16.h>
#include <cstdint>

// Problem constants (Qwen3MoeSparseMoeBlock_2413771621126)
#define T_TOK   1024
#define HID     2048
#define NEXP    16
#define TOPK    4
#define INTER   768
#define INTER2  1536

// ---------------- device scratch (static; allocation-free) ----------------
__device__ int   g_cnt[NEXP];
__device__ int   g_tok[NEXP * T_TOK];
__device__ float g_wt [NEXP * T_TOK];

__device__ __align__(128) __nv_bfloat16 g_xhi[(size_t)T_TOK * HID];
__device__ __align__(128) __nv_bfloat16 g_xlo[(size_t)T_TOK * HID];
__device__ __align__(128) __nv_bfloat16 g_ghi[(size_t)NEXP * HID * INTER2];
__device__ __align__(128) __nv_bfloat16 g_glo[(size_t)NEXP * HID * INTER2];
__device__ __align__(128) __nv_bfloat16 g_dhi[(size_t)NEXP * INTER * HID];
__device__ __align__(128) __nv_bfloat16 g_dlo[(size_t)NEXP * INTER * HID];
__device__ __align__(128) __nv_bfloat16 g_hhi[(size_t)NEXP * T_TOK * INTER];
__device__ __align__(128) __nv_bfloat16 g_hlo[(size_t)NEXP * T_TOK * INTER];

// ---------------- helpers ----------------
__device__ __forceinline__ uint32_t smem_u32(const void* p) {
    uint32_t a;
    asm("{ .reg .u64 t; cvta.to.shared.u64 t, %1; cvt.u32.u64 %0, t; }" : "=r"(a) : "l"(p));
    return a;
}

__device__ __forceinline__ void split4(float4 f, uint2& hi, uint2& lo) {
    __nv_bfloat16 hx = __float2bfloat16(f.x);
    __nv_bfloat16 hy = __float2bfloat16(f.y);
    __nv_bfloat16 hz = __float2bfloat16(f.z);
    __nv_bfloat16 hw = __float2bfloat16(f.w);
    __nv_bfloat16 lx = __float2bfloat16(f.x - __bfloat162float(hx));
    __nv_bfloat16 ly = __float2bfloat16(f.y - __bfloat162float(hy));
    __nv_bfloat16 lz = __float2bfloat16(f.z - __bfloat162float(hz));
    __nv_bfloat16 lw = __float2bfloat16(f.w - __bfloat162float(hw));
    hi.x = ((uint32_t)__bfloat16_as_ushort(hy) << 16) | __bfloat16_as_ushort(hx);
    hi.y = ((uint32_t)__bfloat16_as_ushort(hw) << 16) | __bfloat16_as_ushort(hz);
    lo.x = ((uint32_t)__bfloat16_as_ushort(ly) << 16) | __bfloat16_as_ushort(lx);
    lo.y = ((uint32_t)__bfloat16_as_ushort(lw) << 16) | __bfloat16_as_ushort(lz);
}
__device__ __forceinline__ void split1(float f, uint16_t& hi, uint16_t& lo) {
    __nv_bfloat16 h = __float2bfloat16(f);
    __nv_bfloat16 l = __float2bfloat16(f - __bfloat162float(h));
    hi = __bfloat16_as_ushort(h);
    lo = __bfloat16_as_ushort(l);
}

#define MMA_BF16(d, a, b) \
    asm volatile("mma.sync.aligned.m16n8k16.row.col.f32.bf16.bf16.f32 " \
        "{%0,%1,%2,%3}, {%4,%5,%6,%7}, {%8,%9}, {%0,%1,%2,%3};" \
        : "+f"((d)[0]), "+f"((d)[1]), "+f"((d)[2]), "+f"((d)[3]) \
        : "r"((a)[0]), "r"((a)[1]), "r"((a)[2]), "r"((a)[3]), \
          "r"((b)[0]), "r"((b)[1]))

#define LDSM4(r, a) \
    asm volatile("ldmatrix.sync.aligned.m8n8.x4.shared.b16 {%0,%1,%2,%3}, [%4];" \
        : "=r"((r)[0]), "=r"((r)[1]), "=r"((r)[2]), "=r"((r)[3]) : "r"(a))
#define LDSM4T(r, a) \
    asm volatile("ldmatrix.sync.aligned.m8n8.x4.trans.shared.b16 {%0,%1,%2,%3}, [%4];" \
        : "=r"((r)[0]), "=r"((r)[1]), "=r"((r)[2]), "=r"((r)[3]) : "r"(a))

#define CP16(dst, src) \
    asm volatile("cp.async.cg.shared.global [%0], [%1], 16;" \
        :: "r"(dst), "l"(__cvta_generic_to_global(src)))
#define CP_COMMIT() asm volatile("cp.async.commit_group;" ::: "memory")
#define CP_WAIT1()  asm volatile("cp.async.wait_group 1;" ::: "memory")

// ---------------- phase 0 ----------------
__global__ void zero_kernel(float* __restrict__ out, int n) {
    int i = blockIdx.x * blockDim.x + threadIdx.x;
    if (i < n) out[i] = 0.0f;
    if (blockIdx.x == 0 && threadIdx.x < NEXP) g_cnt[threadIdx.x] = 0;
}

// ---------------- split conversion (fp32 -> hi/lo bf16), 2 float4/thread ----
__global__ void __launch_bounds__(256) split_kernel(
    const float4* __restrict__ src, uint2* __restrict__ hi, uint2* __restrict__ lo, int n4)
{
    int i = (blockIdx.x * blockDim.x + threadIdx.x) * 2;
    if (i + 1 < n4) {
        float4 f0 = src[i], f1 = src[i + 1];
        uint2 h0, l0, h1, l1;
        split4(f0, h0, l0);
        split4(f1, h1, l1);
        hi[i] = h0; hi[i + 1] = h1;
        lo[i] = l0; lo[i + 1] = l1;
    } else if (i < n4) {
        uint2 h, l;
        split4(src[i], h, l);
        hi[i] = h; lo[i] = l;
    }
}

// ---------------- phase 1: router ----------------
__global__ void __launch_bounds__(128) router_kernel(
    const float* __restrict__ x, const float* __restrict__ rw)
{
    int t = blockIdx.x, tid = threadIdx.x;
    float acc[NEXP];
#pragma unroll
    for (int e = 0; e < NEXP; e++) acc[e] = 0.0f;
    const float* xr = x + (size_t)t * HID;
    for (int k = tid; k < HID; k += 128) {
        float xv = xr[k];
#pragma unroll
        for (int e = 0; e < NEXP; e++) acc[e] += xv * rw[e * HID + k];
    }
#pragma unroll
    for (int e = 0; e < NEXP; e++) {
#pragma unroll
        for (int off = 16; off > 0; off >>= 1)
            acc[e] += __shfl_down_sync(0xFFFFFFFFu, acc[e], off);
    }
    __shared__ float spart[4][NEXP];
    int warp = tid >> 5, lane = tid & 31;
    if (lane == 0) {
#pragma unroll
        for (int e = 0; e < NEXP; e++) spart[warp][e] = acc[e];
    }
    __syncthreads();
    if (tid == 0) {
        float logit[NEXP];
#pragma unroll
        for (int e = 0; e < NEXP; e++)
            logit[e] = spart[0][e] + spart[1][e] + spart[2][e] + spart[3][e];
        int idx[TOPK]; float val[TOPK]; bool used[NEXP];
#pragma unroll
        for (int e = 0; e < NEXP; e++) used[e] = false;
#pragma unroll
        for (int k = 0; k < TOPK; k++) {
            float best = -1e30f; int bi = 0;
            for (int e = 0; e < NEXP; e++)
                if (!used[e] && logit[e] > best) { best = logit[e]; bi = e; }
            used[bi] = true; idx[k] = bi; val[k] = best;
        }
        float mx = val[0], s = 0.0f, ev[TOPK];
#pragma unroll
        for (int k = 0; k < TOPK; k++) { ev[k] = expf(val[k] - mx); s += ev[k]; }
        float inv = 1.0f / s;
#pragma unroll
        for (int k = 0; k < TOPK; k++) {
            int e = idx[k];
            int pos = atomicAdd(&g_cnt[e], 1);
            g_tok[e * T_TOK + pos] = t;
            g_wt [e * T_TOK + pos] = ev[k] * inv;
        }
    }
}

// ============================================================
// GEMM smem (per stage, bytes):
//  A (128 x 32 bf16, pitch 80):  AH @ 0 (10240), AL @ 10240
//  gate_up B (32 x 128, pitch 272): BH @ 20480 (8704), BL @ 29184 ; stage 37888
//  down    B (32 x 64,  pitch 144): BH @ 20480 (4608), BL @ 25088 ; stage 29696
//  3-stage pipeline.
// ============================================================
#define GU_STAGE 37888
#define GU_SMEM  (3 * GU_STAGE + 1024)
#define DN_STAGE 29696
#define DN_SMEM  (3 * DN_STAGE + 1024)

// ---------------- phase 2: gate_up GEMM ----------------
__device__ __forceinline__ void gu_load(
    int e, int nbase, int k0, uint32_t sb, const int* stok, int tid)
{
#pragma unroll
    for (int i = 0; i < 2; i++) {
        int c = tid + i * 256;
        int row = c >> 2, seg = c & 3;
        int tok = stok[row];
        size_t off = (size_t)tok * HID + k0 + seg * 8;
        CP16(sb + row * 80 + seg * 16,          g_xhi + off);
        CP16(sb + 10240 + row * 80 + seg * 16,  g_xlo + off);
    }
#pragma unroll
    for (int i = 0; i < 2; i++) {
        int c = tid + i * 256;
        int k = c >> 4, seg = c & 15;
        size_t roff = ((size_t)e * HID + k0 + k) * INTER2;
        int col = (seg < 8) ? (nbase + seg * 8) : (INTER + nbase + (seg - 8) * 8);
        CP16(sb + 20480 + k * 272 + seg * 16, g_ghi + roff + col);
        CP16(sb + 29184 + k * 272 + seg * 16, g_glo + roff + col);
    }
}

__global__ void __launch_bounds__(256, 2) gateup_mma(int dummy)
{
    extern __shared__ char smem[];
    int e = blockIdx.z;
    int cnt = g_cnt[e];
    int mbase = blockIdx.x * 128;        // m fastest: active m-tiles of (e,n) run together
    if (mbase >= cnt) return;
    int nbase = blockIdx.y * 64;

    int tid = threadIdx.x;
    int lane = tid & 31, wid = tid >> 5;
    int wm = (wid & 3) * 32;
    int wn = (wid >> 2) * 32;

    uint32_t sbase = smem_u32(smem);
    int*   stok = (int*)  (smem + 3 * GU_STAGE);
    float* swt  = (float*)(smem + 3 * GU_STAGE + 512);
    if (tid < 128) {
        int gm = mbase + tid;
        stok[tid] = (gm < cnt) ? g_tok[e * T_TOK + gm] : 0;
        swt[tid]  = (gm < cnt) ? g_wt [e * T_TOK + gm] : 0.0f;
    }
    __syncthreads();

    float accG[2][4][4], accU[2][4][4];
#pragma unroll
    for (int i = 0; i < 2; i++)
#pragma unroll
        for (int j = 0; j < 4; j++)
#pragma unroll
            for (int c = 0; c < 4; c++) { accG[i][j][c] = 0.0f; accU[i][j][c] = 0.0f; }

    const int S = HID / 32;   // 64
    gu_load(e, nbase, 0, sbase, stok, tid);
    CP_COMMIT();
    gu_load(e, nbase, 32, sbase + GU_STAGE, stok, tid);
    CP_COMMIT();

    uint32_t bufoff[3] = {0u, (uint32_t)GU_STAGE, (uint32_t)(2 * GU_STAGE)};
    int bc = 0;   // buffer of stage s
    int bl = 2;   // buffer for stage s+2

#pragma unroll 1
    for (int s = 0; s < S; s++) {
        CP_WAIT1();
        __syncthreads();
        if (s + 2 < S)
            gu_load(e, nbase, (s + 2) * 32, sbase + bufoff[bl], stok, tid);
        CP_COMMIT();

        uint32_t st = sbase + bufoff[bc];
#pragma unroll
        for (int ks = 0; ks < 2; ks++) {
            uint32_t ah[2][4], al[2][4];
#pragma unroll
            for (int mt = 0; mt < 2; mt++) {
                uint32_t aa = st + (wm + mt * 16 + (lane & 15)) * 80
                            + (ks * 16 + (lane >> 4) * 8) * 2;
                LDSM4(ah[mt], aa);
                LDSM4(al[mt], aa + 10240);
            }
#pragma unroll
            for (int ng = 0; ng < 2; ng++) {
                uint32_t ba = st + 20480 + (ks * 16 + (lane & 15)) * 272
                            + (wn + ng * 16 + (lane >> 4) * 8) * 2;
                uint32_t bgh[4], bgl[4], buh[4], bul[4];
                LDSM4T(bgh, ba);
                LDSM4T(bgl, ba + 8704);
                LDSM4T(buh, ba + 128);
                LDSM4T(bul, ba + 128 + 8704);
#pragma unroll
                for (int half = 0; half < 2; half++) {
                    int j = ng * 2 + half;
#pragma unroll
                    for (int mt = 0; mt < 2; mt++) {
                        MMA_BF16(accG[mt][j], ah[mt], &bgh[half * 2]);
                        MMA_BF16(accG[mt][j], ah[mt], &bgl[half * 2]);
                        MMA_BF16(accG[mt][j], al[mt], &bgh[half * 2]);
                        MMA_BF16(accU[mt][j], ah[mt], &buh[half * 2]);
                        MMA_BF16(accU[mt][j], ah[mt], &bul[half * 2]);
                        MMA_BF16(accU[mt][j], al[mt], &buh[half * 2]);
                    }
                }
            }
        }
        bc = (bc == 2) ? 0 : bc + 1;
        bl = (bl == 2) ? 0 : bl + 1;
    }

    // epilogue: h = silu(gate) * up * wt -> hi/lo bf16 global
#pragma unroll
    for (int mt = 0; mt < 2; mt++) {
#pragma unroll
        for (int j = 0; j < 4; j++) {
            int col = wn + (j >> 1) * 16 + (j & 1) * 8 + (lane & 3) * 2;
#pragma unroll
            for (int rh = 0; rh < 2; rh++) {
                int m = wm + mt * 16 + (lane >> 2) + rh * 8;
                int gm = mbase + m;
                if (gm >= cnt) continue;
                float w = swt[m];
                float g0 = accG[mt][j][rh * 2 + 0], u0 = accU[mt][j][rh * 2 + 0];
                float g1 = accG[mt][j][rh * 2 + 1], u1 = accU[mt][j][rh * 2 + 1];
                float h0 = (g0 / (1.0f + expf(-g0))) * u0 * w;
                float h1 = (g1 / (1.0f + expf(-g1))) * u1 * w;
                uint16_t h0h, h0l, h1h, h1l;
                split1(h0, h0h, h0l);
                split1(h1, h1h, h1l);
                size_t off = ((size_t)e * T_TOK + gm) * INTER + nbase + col;
                *reinterpret_cast<uint32_t*>(g_hhi + off) = (uint32_t)h0h | ((uint32_t)h1h << 16);
                *reinterpret_cast<uint32_t*>(g_hlo + off) = (uint32_t)h0l | ((uint32_t)h1l << 16);
            }
        }
    }
}

// ---------------- phase 3: down GEMM + atomic scatter ----------------
__device__ __forceinline__ void dn_load(
    int e, int mbase, int nbase, int k0, uint32_t sb, int tid)
{
#pragma unroll
    for (int i = 0; i < 2; i++) {
        int c = tid + i * 256;
        int row = c >> 2, seg = c & 3;
        size_t off = ((size_t)e * T_TOK + mbase + row) * INTER + k0 + seg * 8;
        CP16(sb + row * 80 + seg * 16,         g_hhi + off);
        CP16(sb + 10240 + row * 80 + seg * 16, g_hlo + off);
    }
    {
        int c = tid;
        int k = c >> 3, seg = c & 7;
        size_t off = ((size_t)e * INTER + k0 + k) * HID + nbase + seg * 8;
        CP16(sb + 20480 + k * 144 + seg * 16, g_dhi + off);
        CP16(sb + 25088 + k * 144 + seg * 16, g_dlo + off);
    }
}

__global__ void __launch_bounds__(256, 2) down_mma(float* __restrict__ out)
{
    extern __shared__ char smem[];
    int e = blockIdx.z;
    int cnt = g_cnt[e];
    int mbase = blockIdx.x * 128;        // m fastest
    if (mbase >= cnt) return;
    int nbase = blockIdx.y * 64;

    int tid = threadIdx.x;
    int lane = tid & 31, wid = tid >> 5;
    int wm = (wid & 3) * 32;
    int wn = (wid >> 2) * 32;

    uint32_t sbase = smem_u32(smem);
    int* stok = (int*)(smem + 3 * DN_STAGE);
    if (tid < 128) {
        int gm = mbase + tid;
        stok[tid] = (gm < cnt) ? g_tok[e * T_TOK + gm] : -1;
    }
    __syncthreads();

    float acc[2][4][4];
#pragma unroll
    for (int i = 0; i < 2; i++)
#pragma unroll
        for (int j = 0; j < 4; j++)
#pragma unroll
            for (int c = 0; c < 4; c++) acc[i][j][c] = 0.0f;

    const int S = INTER / 32;  // 24
    dn_load(e, mbase, nbase, 0, sbase, tid);
    CP_COMMIT();
    dn_load(e, mbase, nbase, 32, sbase + DN_STAGE, tid);
    CP_COMMIT();

    uint32_t bufoff[3] = {0u, (uint32_t)DN_STAGE, (uint32_t)(2 * DN_STAGE)};
    int bc = 0, bl = 2;

#pragma unroll 1
    for (int s = 0; s < S; s++) {
        CP_WAIT1();
        __syncthreads();
        if (s + 2 < S)
            dn_load(e, mbase, nbase, (s + 2) * 32, sbase + bufoff[bl], tid);
        CP_COMMIT();

        uint32_t st = sbase + bufoff[bc];
#pragma unroll
        for (int ks = 0; ks < 2; ks++) {
            uint32_t ah[2][4], al[2][4];
#pragma unroll
            for (int mt = 0; mt < 2; mt++) {
                uint32_t aa = st + (wm + mt * 16 + (lane & 15)) * 80
                            + (ks * 16 + (lane >> 4) * 8) * 2;
                LDSM4(ah[mt], aa);
                LDSM4(al[mt], aa + 10240);
            }
#pragma unroll
            for (int ng = 0; ng < 2; ng++) {
                uint32_t ba = st + 20480 + (ks * 16 + (lane & 15)) * 144
                            + (wn + ng * 16 + (lane >> 4) * 8) * 2;
                uint32_t bh[4], bl2[4];
                LDSM4T(bh, ba);
                LDSM4T(bl2, ba + 4608);
#pragma unroll
                for (int half = 0; half < 2; half++) {
                    int j = ng * 2 + half;
#pragma unroll
                    for (int mt = 0; mt < 2; mt++) {
                        MMA_BF16(acc[mt][j], ah[mt], &bh[half * 2]);
                        MMA_BF16(acc[mt][j], ah[mt], &bl2[half * 2]);
                        MMA_BF16(acc[mt][j], al[mt], &bh[half * 2]);
                    }
                }
            }
        }
        bc = (bc == 2) ? 0 : bc + 1;
        bl = (bl == 2) ? 0 : bl + 1;
    }

    // epilogue: atomic scatter into out
#pragma unroll
    for (int mt = 0; mt < 2; mt++) {
#pragma unroll
        for (int rh = 0; rh < 2; rh++) {
            int m = wm + mt * 16 + (lane >> 2) + rh * 8;
            int tok = stok[m];
            if (tok < 0) continue;
            float* op = &out[(size_t)tok * HID + nbase];
#pragma unroll
            for (int j = 0; j < 4; j++) {
                int col = wn + (j >> 1) * 16 + (j & 1) * 8 + (lane & 3) * 2;
                atomicAdd(op + col,     acc[mt][j][rh * 2 + 0]);
                atomicAdd(op + col + 1, acc[mt][j][rh * 2 + 1]);
            }
        }
    }
}

// ---------------- launch ----------------
extern "C" void kernel_launch(void* const* d_in, const int* in_sizes, int n_in,
                              void* d_out, int out_size)
{
    const float* x    = (const float*)d_in[0];
    const float* rw   = (const float*)d_in[1];
    const float* gup  = (const float*)d_in[2];
    const float* dw   = (const float*)d_in[3];
    float* out = (float*)d_out;

    static bool attr_set = false;
    if (!attr_set) {
        cudaFuncSetAttribute(gateup_mma, cudaFuncAttributeMaxDynamicSharedMemorySize, GU_SMEM);
        cudaFuncSetAttribute(down_mma,   cudaFuncAttributeMaxDynamicSharedMemorySize, DN_SMEM);
        attr_set = true;
    }

    int n_out = T_TOK * HID;
    zero_kernel<<<(n_out + 511) / 512, 512>>>(out, n_out);
    router_kernel<<<T_TOK, 128>>>(x, rw);

    // preconversion (hi/lo bf16 split)
    {
        __nv_bfloat16 *xhi, *xlo, *ghi, *glo, *dhi, *dlo;
        cudaGetSymbolAddress((void**)&xhi, g_xhi);
        cudaGetSymbolAddress((void**)&xlo, g_xlo);
        cudaGetSymbolAddress((void**)&ghi, g_ghi);
        cudaGetSymbolAddress((void**)&glo, g_glo);
        cudaGetSymbolAddress((void**)&dhi, g_dhi);
        cudaGetSymbolAddress((void**)&dlo, g_dlo);

        int n4x = T_TOK * HID / 4;
        split_kernel<<<(n4x + 511) / 512, 256>>>(
            (const float4*)x, (uint2*)xhi, (uint2*)xlo, n4x);
        int n4g = NEXP * HID * INTER2 / 4;
        split_kernel<<<(n4g + 511) / 512, 256>>>(
            (const float4*)gup, (uint2*)ghi, (uint2*)glo, n4g);
        int n4d = NEXP * INTER * HID / 4;
        split_kernel<<<(n4d + 511) / 512, 256>>>(
            (const float4*)dw, (uint2*)dhi, (uint2*)dlo, n4d);
    }

    dim3 gridG(T_TOK / 128, INTER / 64, NEXP);   // (m=8, n=12, e=16)
    gateup_mma<<<gridG, 256, GU_SMEM>>>(0);

    dim3 gridD(T_TOK / 128, HID / 64, NEXP);     // (m=8, n=32, e=16)
    down_mma<<<gridD, 256, DN_SMEM>>>(out);
}